// round 3
// baseline (speedup 1.0000x reference)
#include <cuda_runtime.h>
#include <stdint.h>

#define N_NODES 50000
#define N_EDGES 800000
#define IN_C    128
#define HID_C   128
#define OUT_C   64

// ---------------- scratch (static device globals; no allocation) ------------
__device__ int   g_cnt   [N_NODES];
__device__ int   g_rowptr[N_NODES + 1];
__device__ int   g_cursor[N_NODES];
__device__ int   g_csr   [N_EDGES];
__device__ float g_dinv  [N_NODES];
__device__ float g_h1    [N_NODES * HID_C];   // pre-scaled GEMM1 output
__device__ float g_x2    [N_NODES * HID_C];   // relu(layer-1 out) = layer-2 input
__device__ float g_h2    [N_NODES * OUT_C];   // pre-scaled GEMM2 output

// ---------------- CSR build ---------------------------------------------------
__global__ void k_count(const int* __restrict__ dst) {
    int e = blockIdx.x * blockDim.x + threadIdx.x;
    if (e < N_EDGES) atomicAdd(&g_cnt[dst[e]], 1);
}

// single-block exclusive scan over 50k counts; also produces dinv + cursor
__global__ __launch_bounds__(1024)
void k_scan() {
    __shared__ int ssum[1024];
    const int t  = threadIdx.x;
    const int CH = (N_NODES + 1023) / 1024;          // 49
    int beg = t * CH;
    int end = beg + CH; if (end > N_NODES) end = N_NODES;
    if (beg > N_NODES) beg = N_NODES;

    int s = 0;
    for (int i = beg; i < end; i++) s += g_cnt[i];
    ssum[t] = s;
    __syncthreads();
    for (int off = 1; off < 1024; off <<= 1) {
        int v = (t >= off) ? ssum[t - off] : 0;
        __syncthreads();
        ssum[t] += v;
        __syncthreads();
    }
    int run = (t == 0) ? 0 : ssum[t - 1];
    for (int i = beg; i < end; i++) {
        int c = g_cnt[i];
        g_rowptr[i] = run;
        g_cursor[i] = run;
        g_dinv[i]   = rsqrtf(1.0f + (float)c);       // +1 self loop
        run += c;
    }
    if (t == 1023) g_rowptr[N_NODES] = run;
}

__global__ void k_place(const int* __restrict__ src, const int* __restrict__ dst) {
    int e = blockIdx.x * blockDim.x + threadIdx.x;
    if (e >= N_EDGES) return;
    int d = dst[e];
    int idx = atomicAdd(&g_cursor[d], 1);
    g_csr[idx] = src[e];
}

// ---------------- GEMM: H = (X @ W) * dinv[row] -------------------------------
// 128 x COUT block tile, 256 threads, 8 x (COUT/16) per thread.
template <int COUT>
__global__ __launch_bounds__(256)
void k_gemm(const float* __restrict__ X, const float* __restrict__ W,
            float* __restrict__ H)
{
    constexpr int BM = 128;
    constexpr int BK = 16;
    constexpr int TN = COUT / 16;                    // 8 (layer1) / 4 (layer2)

    __shared__ float sX[BM][BK];                     // row-major, 64B rows (conflict-free f4 stores)
    __shared__ float sW[BK][COUT];

    const int tid = threadIdx.x;
    const int tx  = tid & 15;                        // column group
    const int ty  = tid >> 4;                        // row group
    const int row0 = blockIdx.x * BM;

    float acc[8][TN];
#pragma unroll
    for (int i = 0; i < 8; i++)
#pragma unroll
        for (int j = 0; j < TN; j++) acc[i][j] = 0.f;

    for (int k0 = 0; k0 < IN_C; k0 += BK) {
        // X tile: 128 rows x 16 cols = 512 float4, 2 per thread
#pragma unroll
        for (int i = tid; i < BM * BK / 4; i += 256) {
            int r = i >> 2, q = i & 3;
            int gr = row0 + r;
            float4 v = make_float4(0.f, 0.f, 0.f, 0.f);
            if (gr < N_NODES)
                v = *reinterpret_cast<const float4*>(X + (size_t)gr * IN_C + k0 + 4 * q);
            *reinterpret_cast<float4*>(&sX[r][4 * q]) = v;
        }
        // W tile: rows k0..k0+15 contiguous in memory
        {
            const float4* wsrc = reinterpret_cast<const float4*>(W + (size_t)k0 * COUT);
            float4* wdst = reinterpret_cast<float4*>(&sW[0][0]);
#pragma unroll
            for (int i = tid; i < BK * COUT / 4; i += 256) wdst[i] = wsrc[i];
        }
        __syncthreads();

#pragma unroll
        for (int k = 0; k < BK; k++) {
            float a[8];
#pragma unroll
            for (int i = 0; i < 8; i++) a[i] = sX[ty * 8 + i][k];   // broadcast LDS
            float w[TN];
            {
                float4 w0 = *reinterpret_cast<const float4*>(&sW[k][tx * TN]);
                w[0] = w0.x; w[1] = w0.y; w[2] = w0.z; w[3] = w0.w;
                if (TN == 8) {
                    float4 w1 = *reinterpret_cast<const float4*>(&sW[k][tx * TN + 4]);
                    w[4] = w1.x; w[5] = w1.y; w[6] = w1.z; w[7] = w1.w;
                }
            }
#pragma unroll
            for (int i = 0; i < 8; i++)
#pragma unroll
                for (int j = 0; j < TN; j++)
                    acc[i][j] = fmaf(a[i], w[j], acc[i][j]);
        }
        __syncthreads();
    }

#pragma unroll
    for (int i = 0; i < 8; i++) {
        int gr = row0 + ty * 8 + i;
        if (gr < N_NODES) {
            float dv = g_dinv[gr];
#pragma unroll
            for (int jj = 0; jj < TN / 4; jj++) {
                float4 o = make_float4(acc[i][4 * jj + 0] * dv, acc[i][4 * jj + 1] * dv,
                                       acc[i][4 * jj + 2] * dv, acc[i][4 * jj + 3] * dv);
                *reinterpret_cast<float4*>(H + (size_t)gr * COUT + tx * TN + 4 * jj) = o;
            }
        }
    }
}

// ---------------- layer-1 aggregation: warp per node --------------------------
// x2[n] = relu( dinv[n] * (h1[n] + sum_{s in in(n)} h1[s]) + b1 )
__global__ __launch_bounds__(256)
void k_agg1(const float* __restrict__ b1) {
    int gw   = (blockIdx.x * 256 + threadIdx.x) >> 5;
    int lane = threadIdx.x & 31;
    if (gw >= N_NODES) return;
    const int n = gw;

    const float4* Hq = reinterpret_cast<const float4*>(g_h1);
    float4 a0 = Hq[(size_t)n * 32 + lane];            // self loop (pre-scaled)
    float4 a1 = make_float4(0.f, 0.f, 0.f, 0.f);
    float4 a2 = make_float4(0.f, 0.f, 0.f, 0.f);
    float4 a3 = make_float4(0.f, 0.f, 0.f, 0.f);

    int e   = __ldg(&g_rowptr[n]);
    int end = __ldg(&g_rowptr[n + 1]);

    for (; e + 3 < end; e += 4) {
        int s0 = __ldg(&g_csr[e]);
        int s1 = __ldg(&g_csr[e + 1]);
        int s2 = __ldg(&g_csr[e + 2]);
        int s3 = __ldg(&g_csr[e + 3]);
        float4 v0 = __ldcg(&Hq[(size_t)s0 * 32 + lane]);
        float4 v1 = __ldcg(&Hq[(size_t)s1 * 32 + lane]);
        float4 v2 = __ldcg(&Hq[(size_t)s2 * 32 + lane]);
        float4 v3 = __ldcg(&Hq[(size_t)s3 * 32 + lane]);
        a0.x += v0.x; a0.y += v0.y; a0.z += v0.z; a0.w += v0.w;
        a1.x += v1.x; a1.y += v1.y; a1.z += v1.z; a1.w += v1.w;
        a2.x += v2.x; a2.y += v2.y; a2.z += v2.z; a2.w += v2.w;
        a3.x += v3.x; a3.y += v3.y; a3.z += v3.z; a3.w += v3.w;
    }
    for (; e < end; e++) {
        int s = __ldg(&g_csr[e]);
        float4 v = __ldcg(&Hq[(size_t)s * 32 + lane]);
        a0.x += v.x; a0.y += v.y; a0.z += v.z; a0.w += v.w;
    }
    a0.x += a1.x + a2.x + a3.x;
    a0.y += a1.y + a2.y + a3.y;
    a0.z += a1.z + a2.z + a3.z;
    a0.w += a1.w + a2.w + a3.w;

    float dv = g_dinv[n];
    float4 b = reinterpret_cast<const float4*>(b1)[lane];
    float4 o;
    o.x = fmaxf(fmaf(a0.x, dv, b.x), 0.f);
    o.y = fmaxf(fmaf(a0.y, dv, b.y), 0.f);
    o.z = fmaxf(fmaf(a0.z, dv, b.z), 0.f);
    o.w = fmaxf(fmaf(a0.w, dv, b.w), 0.f);
    reinterpret_cast<float4*>(g_x2)[(size_t)n * 32 + lane] = o;
}

// ---------------- layer-2 aggregation: half-warp per node ---------------------
// out[n] = dinv[n] * (h2[n] + sum h2[s]) + b2
__global__ __launch_bounds__(256)
void k_agg2(float* __restrict__ out, const float* __restrict__ b2) {
    int gw   = (blockIdx.x * 256 + threadIdx.x) >> 5;
    int lane = threadIdx.x & 31;
    int half = lane >> 4;
    int hl   = lane & 15;
    int n    = gw * 2 + half;
    if (n >= N_NODES) return;

    const float4* Hq = reinterpret_cast<const float4*>(g_h2);
    float4 a0 = Hq[(size_t)n * 16 + hl];              // self loop (pre-scaled)
    float4 a1 = make_float4(0.f, 0.f, 0.f, 0.f);
    float4 a2 = make_float4(0.f, 0.f, 0.f, 0.f);
    float4 a3 = make_float4(0.f, 0.f, 0.f, 0.f);

    int e   = __ldg(&g_rowptr[n]);
    int end = __ldg(&g_rowptr[n + 1]);

    for (; e + 3 < end; e += 4) {
        int s0 = __ldg(&g_csr[e]);
        int s1 = __ldg(&g_csr[e + 1]);
        int s2 = __ldg(&g_csr[e + 2]);
        int s3 = __ldg(&g_csr[e + 3]);
        float4 v0 = __ldcg(&Hq[(size_t)s0 * 16 + hl]);
        float4 v1 = __ldcg(&Hq[(size_t)s1 * 16 + hl]);
        float4 v2 = __ldcg(&Hq[(size_t)s2 * 16 + hl]);
        float4 v3 = __ldcg(&Hq[(size_t)s3 * 16 + hl]);
        a0.x += v0.x; a0.y += v0.y; a0.z += v0.z; a0.w += v0.w;
        a1.x += v1.x; a1.y += v1.y; a1.z += v1.z; a1.w += v1.w;
        a2.x += v2.x; a2.y += v2.y; a2.z += v2.z; a2.w += v2.w;
        a3.x += v3.x; a3.y += v3.y; a3.z += v3.z; a3.w += v3.w;
    }
    for (; e < end; e++) {
        int s = __ldg(&g_csr[e]);
        float4 v = __ldcg(&Hq[(size_t)s * 16 + hl]);
        a0.x += v.x; a0.y += v.y; a0.z += v.z; a0.w += v.w;
    }
    a0.x += a1.x + a2.x + a3.x;
    a0.y += a1.y + a2.y + a3.y;
    a0.z += a1.z + a2.z + a3.z;
    a0.w += a1.w + a2.w + a3.w;

    float dv = g_dinv[n];
    float4 b = reinterpret_cast<const float4*>(b2)[hl];
    float4 o;
    o.x = fmaf(a0.x, dv, b.x);
    o.y = fmaf(a0.y, dv, b.y);
    o.z = fmaf(a0.z, dv, b.z);
    o.w = fmaf(a0.w, dv, b.w);
    reinterpret_cast<float4*>(out)[(size_t)n * 16 + hl] = o;
}

// ---------------- launch -------------------------------------------------------
extern "C" void kernel_launch(void* const* d_in, const int* in_sizes, int n_in,
                              void* d_out, int out_size)
{
    const float* x  = (const float*)d_in[0];
    const int*   ei = (const int*)  d_in[1];
    const float* W1 = (const float*)d_in[2];
    const float* b1 = (const float*)d_in[3];
    const float* W2 = (const float*)d_in[4];
    const float* b2 = (const float*)d_in[5];
    float* out = (float*)d_out;

    const int* srcp = ei;             // edge_index[0]
    const int* dstp = ei + N_EDGES;   // edge_index[1]

    float *h1, *x2, *h2;
    void* cntp;
    cudaGetSymbolAddress((void**)&h1, g_h1);
    cudaGetSymbolAddress((void**)&x2, g_x2);
    cudaGetSymbolAddress((void**)&h2, g_h2);
    cudaGetSymbolAddress(&cntp, g_cnt);

    // CSR build + dinv
    cudaMemsetAsync(cntp, 0, N_NODES * sizeof(int));
    k_count<<<(N_EDGES + 255) / 256, 256>>>(dstp);
    k_scan <<<1, 1024>>>();
    k_place<<<(N_EDGES + 255) / 256, 256>>>(srcp, dstp);

    const int gemm_blocks = (N_NODES + 127) / 128;

    // ---- layer 1 ----
    k_gemm<HID_C><<<gemm_blocks, 256>>>(x, W1, h1);
    k_agg1<<<(N_NODES * 32 + 255) / 256, 256>>>(b1);

    // ---- layer 2 ----
    k_gemm<OUT_C><<<gemm_blocks, 256>>>(x2, W2, h2);
    k_agg2<<<((N_NODES + 1) / 2 * 32 + 255) / 256, 256>>>(out, b2);
}

// round 4
// speedup vs baseline: 1.1271x; 1.1271x over previous
#include <cuda_runtime.h>
#include <stdint.h>

#define N_NODES 50000
#define N_EDGES 800000
#define IN_C    128
#define HID_C   128
#define OUT_C   64
#define SCAN_BLK 196   // ceil(50000/256)

typedef unsigned long long ull;
union F2U { ull u; float2 f; };

// ---------------- scratch (static device globals; no allocation) ------------
__device__ int   g_cnt   [N_NODES];
__device__ int   g_bsum  [SCAN_BLK];
__device__ int   g_boff  [SCAN_BLK];
__device__ int   g_rowptr[N_NODES + 1];
__device__ int   g_cursor[N_NODES];
__device__ int   g_csr   [N_EDGES];
__device__ float g_dinv  [N_NODES];
__device__ float g_h1    [N_NODES * HID_C];
__device__ float g_x2    [N_NODES * HID_C];
__device__ float g_h2    [N_NODES * OUT_C];

// ---------------- packed fp32x2 FMA ------------------------------------------
__device__ __forceinline__ ull fma2(ull a, ull b, ull c) {
    ull d;
    asm("fma.rn.f32x2 %0, %1, %2, %3;" : "=l"(d) : "l"(a), "l"(b), "l"(c));
    return d;
}

// ---------------- CSR build ---------------------------------------------------
__global__ void k_count(const int* __restrict__ dst) {
    int t = blockIdx.x * blockDim.x + threadIdx.x;
    if (t >= N_EDGES / 4) return;
    int4 d4 = reinterpret_cast<const int4*>(dst)[t];
    atomicAdd(&g_cnt[d4.x], 1);
    atomicAdd(&g_cnt[d4.y], 1);
    atomicAdd(&g_cnt[d4.z], 1);
    atomicAdd(&g_cnt[d4.w], 1);
}

__global__ void k_scan1() {
    __shared__ int s[256];
    int i = blockIdx.x * 256 + threadIdx.x;
    int c = (i < N_NODES) ? g_cnt[i] : 0;
    s[threadIdx.x] = c;
    __syncthreads();
#pragma unroll
    for (int o = 128; o > 0; o >>= 1) {
        if (threadIdx.x < o) s[threadIdx.x] += s[threadIdx.x + o];
        __syncthreads();
    }
    if (threadIdx.x == 0) g_bsum[blockIdx.x] = s[0];
}

__global__ void k_scan2() {
    __shared__ int s[256];
    int t = threadIdx.x;
    int own = (t < SCAN_BLK) ? g_bsum[t] : 0;
    s[t] = own;
    __syncthreads();
#pragma unroll
    for (int o = 1; o < 256; o <<= 1) {
        int v = (t >= o) ? s[t - o] : 0;
        __syncthreads();
        s[t] += v;
        __syncthreads();
    }
    if (t < SCAN_BLK) g_boff[t] = s[t] - own;      // exclusive block offsets
}

__global__ void k_scan3() {
    __shared__ int s[256];
    int t = threadIdx.x;
    int i = blockIdx.x * 256 + t;
    int c = (i < N_NODES) ? g_cnt[i] : 0;
    s[t] = c;
    __syncthreads();
#pragma unroll
    for (int o = 1; o < 256; o <<= 1) {
        int v = (t >= o) ? s[t - o] : 0;
        __syncthreads();
        s[t] += v;
        __syncthreads();
    }
    if (i < N_NODES) {
        int excl = g_boff[blockIdx.x] + s[t] - c;
        g_rowptr[i] = excl;
        g_cursor[i] = excl;
        g_dinv[i]   = rsqrtf(1.0f + (float)c);     // +1 self loop
        if (i == N_NODES - 1) g_rowptr[N_NODES] = excl + c;
    }
}

__global__ void k_place(const int* __restrict__ src, const int* __restrict__ dst) {
    int t = blockIdx.x * blockDim.x + threadIdx.x;
    if (t >= N_EDGES / 4) return;
    int4 d4 = reinterpret_cast<const int4*>(dst)[t];
    int4 s4 = reinterpret_cast<const int4*>(src)[t];
    int i0 = atomicAdd(&g_cursor[d4.x], 1);
    int i1 = atomicAdd(&g_cursor[d4.y], 1);
    int i2 = atomicAdd(&g_cursor[d4.z], 1);
    int i3 = atomicAdd(&g_cursor[d4.w], 1);
    g_csr[i0] = s4.x;
    g_csr[i1] = s4.y;
    g_csr[i2] = s4.z;
    g_csr[i3] = s4.w;
}

// ---------------- GEMM: H = (X @ W) * dinv[row], packed fp32x2 ----------------
// BM=64 x COUT tile, 256 threads. Per thread: RPT rows (as RPT/2 M-pairs) x 4 cols.
// a-pairs come packed from transposed X tile (LDS.64);
// w comes duplicated from sW2 so (w,w) operands are direct LDS.128 halves.
template <int COUT>
__global__ __launch_bounds__(256)
void k_gemm(const float* __restrict__ X, const float* __restrict__ W,
            float* __restrict__ H)
{
    constexpr int BM  = 64;
    constexpr int BK  = 32;
    constexpr int CQ  = COUT / 4;      // 32 / 16
    constexpr int RT  = 256 / CQ;      // 8 / 16
    constexpr int RPT = BM / RT;       // 8 / 4
    constexpr int NP  = RPT / 2;       // 4 / 2

    __shared__ float sXT[BK][BM];           // transposed X tile
    __shared__ float sW2[BK][2 * COUT];     // duplicated W tile

    const int tid  = threadIdx.x;
    const int colq = tid % CQ;
    const int rgrp = tid / CQ;
    const int row0 = blockIdx.x * BM;

    ull acc[NP][4];
#pragma unroll
    for (int p = 0; p < NP; p++)
#pragma unroll
        for (int j = 0; j < 4; j++) acc[p][j] = 0ull;

    for (int k0 = 0; k0 < IN_C; k0 += BK) {
        // X tile: 64 rows x 32 cols, stored transposed. 512 float4 / 256 thr.
#pragma unroll
        for (int i = tid; i < BM * BK / 4; i += 256) {
            int r = i >> 3, q = i & 7;
            int gr = row0 + r;
            float4 v = make_float4(0.f, 0.f, 0.f, 0.f);
            if (gr < N_NODES)
                v = *reinterpret_cast<const float4*>(X + (size_t)gr * IN_C + k0 + 4 * q);
            sXT[4 * q + 0][r] = v.x;
            sXT[4 * q + 1][r] = v.y;
            sXT[4 * q + 2][r] = v.z;
            sXT[4 * q + 3][r] = v.w;
        }
        // W tile, duplicated: sW2[k][2j] = sW2[k][2j+1] = W[k0+k][j]
#pragma unroll
        for (int i = tid; i < BK * COUT / 4; i += 256) {
            int k = i / (COUT / 4), q = i % (COUT / 4);
            float4 v = *reinterpret_cast<const float4*>(W + (size_t)(k0 + k) * COUT + 4 * q);
            float2* dp = reinterpret_cast<float2*>(&sW2[k][8 * q]);
            dp[0] = make_float2(v.x, v.x);
            dp[1] = make_float2(v.y, v.y);
            dp[2] = make_float2(v.z, v.z);
            dp[3] = make_float2(v.w, v.w);
        }
        __syncthreads();

#pragma unroll
        for (int k = 0; k < BK; k++) {
            ulonglong2 w01 = *reinterpret_cast<const ulonglong2*>(&sW2[k][8 * colq]);
            ulonglong2 w23 = *reinterpret_cast<const ulonglong2*>(&sW2[k][8 * colq + 4]);
            ull wd[4] = {w01.x, w01.y, w23.x, w23.y};

            ull ap[NP];
            const ull* app = reinterpret_cast<const ull*>(&sXT[k][rgrp * RPT]);
#pragma unroll
            for (int p = 0; p < NP; p++) ap[p] = app[p];

#pragma unroll
            for (int p = 0; p < NP; p++)
#pragma unroll
                for (int j = 0; j < 4; j++)
                    acc[p][j] = fma2(ap[p], wd[j], acc[p][j]);
        }
        __syncthreads();
    }

#pragma unroll
    for (int p = 0; p < NP; p++) {
        int r0 = row0 + rgrp * RPT + 2 * p;
        int r1 = r0 + 1;
        F2U u0, u1, u2, u3;
        u0.u = acc[p][0]; u1.u = acc[p][1]; u2.u = acc[p][2]; u3.u = acc[p][3];
        if (r0 < N_NODES) {
            float dv = g_dinv[r0];
            float4 o = make_float4(u0.f.x * dv, u1.f.x * dv, u2.f.x * dv, u3.f.x * dv);
            *reinterpret_cast<float4*>(H + (size_t)r0 * COUT + 4 * colq) = o;
        }
        if (r1 < N_NODES) {
            float dv = g_dinv[r1];
            float4 o = make_float4(u0.f.y * dv, u1.f.y * dv, u2.f.y * dv, u3.f.y * dv);
            *reinterpret_cast<float4*>(H + (size_t)r1 * COUT + 4 * colq) = o;
        }
    }
}

// ---------------- layer-1 aggregation: warp per node, unroll 8 ----------------
__global__ __launch_bounds__(256)
void k_agg1(const float* __restrict__ b1) {
    int gw   = (blockIdx.x * 256 + threadIdx.x) >> 5;
    int lane = threadIdx.x & 31;
    if (gw >= N_NODES) return;

    const float4* Hq = reinterpret_cast<const float4*>(g_h1);
    float4 a0 = __ldcg(&Hq[(size_t)gw * 32 + lane]);   // self loop (pre-scaled)
    float4 a1 = make_float4(0.f, 0.f, 0.f, 0.f);
    float4 a2 = make_float4(0.f, 0.f, 0.f, 0.f);
    float4 a3 = make_float4(0.f, 0.f, 0.f, 0.f);

    int e   = __ldg(&g_rowptr[gw]);
    int end = __ldg(&g_rowptr[gw + 1]);

    for (; e + 8 <= end; e += 8) {
        int s0 = __ldg(&g_csr[e + 0]), s1 = __ldg(&g_csr[e + 1]);
        int s2 = __ldg(&g_csr[e + 2]), s3 = __ldg(&g_csr[e + 3]);
        int s4 = __ldg(&g_csr[e + 4]), s5 = __ldg(&g_csr[e + 5]);
        int s6 = __ldg(&g_csr[e + 6]), s7 = __ldg(&g_csr[e + 7]);
        float4 v0 = __ldcg(&Hq[(size_t)s0 * 32 + lane]);
        float4 v1 = __ldcg(&Hq[(size_t)s1 * 32 + lane]);
        float4 v2 = __ldcg(&Hq[(size_t)s2 * 32 + lane]);
        float4 v3 = __ldcg(&Hq[(size_t)s3 * 32 + lane]);
        float4 v4 = __ldcg(&Hq[(size_t)s4 * 32 + lane]);
        float4 v5 = __ldcg(&Hq[(size_t)s5 * 32 + lane]);
        float4 v6 = __ldcg(&Hq[(size_t)s6 * 32 + lane]);
        float4 v7 = __ldcg(&Hq[(size_t)s7 * 32 + lane]);
        a0.x += v0.x; a0.y += v0.y; a0.z += v0.z; a0.w += v0.w;
        a1.x += v1.x; a1.y += v1.y; a1.z += v1.z; a1.w += v1.w;
        a2.x += v2.x; a2.y += v2.y; a2.z += v2.z; a2.w += v2.w;
        a3.x += v3.x; a3.y += v3.y; a3.z += v3.z; a3.w += v3.w;
        a0.x += v4.x; a0.y += v4.y; a0.z += v4.z; a0.w += v4.w;
        a1.x += v5.x; a1.y += v5.y; a1.z += v5.z; a1.w += v5.w;
        a2.x += v6.x; a2.y += v6.y; a2.z += v6.z; a2.w += v6.w;
        a3.x += v7.x; a3.y += v7.y; a3.z += v7.z; a3.w += v7.w;
    }
    for (; e < end; e++) {
        int s = __ldg(&g_csr[e]);
        float4 v = __ldcg(&Hq[(size_t)s * 32 + lane]);
        a0.x += v.x; a0.y += v.y; a0.z += v.z; a0.w += v.w;
    }
    a0.x += a1.x + a2.x + a3.x;
    a0.y += a1.y + a2.y + a3.y;
    a0.z += a1.z + a2.z + a3.z;
    a0.w += a1.w + a2.w + a3.w;

    float dv = g_dinv[gw];
    float4 b = reinterpret_cast<const float4*>(b1)[lane];
    float4 o;
    o.x = fmaxf(fmaf(a0.x, dv, b.x), 0.f);
    o.y = fmaxf(fmaf(a0.y, dv, b.y), 0.f);
    o.z = fmaxf(fmaf(a0.z, dv, b.z), 0.f);
    o.w = fmaxf(fmaf(a0.w, dv, b.w), 0.f);
    reinterpret_cast<float4*>(g_x2)[(size_t)gw * 32 + lane] = o;
}

// ---------------- layer-2 aggregation: half-warp per node, unroll 8 -----------
__global__ __launch_bounds__(256)
void k_agg2(float* __restrict__ out, const float* __restrict__ b2) {
    int gw   = (blockIdx.x * 256 + threadIdx.x) >> 5;
    int lane = threadIdx.x & 31;
    int n    = gw * 2 + (lane >> 4);
    int hl   = lane & 15;
    if (n >= N_NODES) return;

    const float4* Hq = reinterpret_cast<const float4*>(g_h2);
    float4 a0 = __ldcg(&Hq[(size_t)n * 16 + hl]);      // self loop (pre-scaled)
    float4 a1 = make_float4(0.f, 0.f, 0.f, 0.f);
    float4 a2 = make_float4(0.f, 0.f, 0.f, 0.f);
    float4 a3 = make_float4(0.f, 0.f, 0.f, 0.f);

    int e   = __ldg(&g_rowptr[n]);
    int end = __ldg(&g_rowptr[n + 1]);

    for (; e + 8 <= end; e += 8) {
        int s0 = __ldg(&g_csr[e + 0]), s1 = __ldg(&g_csr[e + 1]);
        int s2 = __ldg(&g_csr[e + 2]), s3 = __ldg(&g_csr[e + 3]);
        int s4 = __ldg(&g_csr[e + 4]), s5 = __ldg(&g_csr[e + 5]);
        int s6 = __ldg(&g_csr[e + 6]), s7 = __ldg(&g_csr[e + 7]);
        float4 v0 = __ldcg(&Hq[(size_t)s0 * 16 + hl]);
        float4 v1 = __ldcg(&Hq[(size_t)s1 * 16 + hl]);
        float4 v2 = __ldcg(&Hq[(size_t)s2 * 16 + hl]);
        float4 v3 = __ldcg(&Hq[(size_t)s3 * 16 + hl]);
        float4 v4 = __ldcg(&Hq[(size_t)s4 * 16 + hl]);
        float4 v5 = __ldcg(&Hq[(size_t)s5 * 16 + hl]);
        float4 v6 = __ldcg(&Hq[(size_t)s6 * 16 + hl]);
        float4 v7 = __ldcg(&Hq[(size_t)s7 * 16 + hl]);
        a0.x += v0.x; a0.y += v0.y; a0.z += v0.z; a0.w += v0.w;
        a1.x += v1.x; a1.y += v1.y; a1.z += v1.z; a1.w += v1.w;
        a2.x += v2.x; a2.y += v2.y; a2.z += v2.z; a2.w += v2.w;
        a3.x += v3.x; a3.y += v3.y; a3.z += v3.z; a3.w += v3.w;
        a0.x += v4.x; a0.y += v4.y; a0.z += v4.z; a0.w += v4.w;
        a1.x += v5.x; a1.y += v5.y; a1.z += v5.z; a1.w += v5.w;
        a2.x += v6.x; a2.y += v6.y; a2.z += v6.z; a2.w += v6.w;
        a3.x += v7.x; a3.y += v7.y; a3.z += v7.z; a3.w += v7.w;
    }
    for (; e < end; e++) {
        int s = __ldg(&g_csr[e]);
        float4 v = __ldcg(&Hq[(size_t)s * 16 + hl]);
        a0.x += v.x; a0.y += v.y; a0.z += v.z; a0.w += v.w;
    }
    a0.x += a1.x + a2.x + a3.x;
    a0.y += a1.y + a2.y + a3.y;
    a0.z += a1.z + a2.z + a3.z;
    a0.w += a1.w + a2.w + a3.w;

    float dv = g_dinv[n];
    float4 b = reinterpret_cast<const float4*>(b2)[hl];
    float4 o;
    o.x = fmaf(a0.x, dv, b.x);
    o.y = fmaf(a0.y, dv, b.y);
    o.z = fmaf(a0.z, dv, b.z);
    o.w = fmaf(a0.w, dv, b.w);
    reinterpret_cast<float4*>(out)[(size_t)n * 16 + hl] = o;
}

// ---------------- launch -------------------------------------------------------
extern "C" void kernel_launch(void* const* d_in, const int* in_sizes, int n_in,
                              void* d_out, int out_size)
{
    const float* x  = (const float*)d_in[0];
    const int*   ei = (const int*)  d_in[1];
    const float* W1 = (const float*)d_in[2];
    const float* b1 = (const float*)d_in[3];
    const float* W2 = (const float*)d_in[4];
    const float* b2 = (const float*)d_in[5];
    float* out = (float*)d_out;

    const int* srcp = ei;             // edge_index[0]
    const int* dstp = ei + N_EDGES;   // edge_index[1]

    float *h1, *x2, *h2;
    void* cntp;
    cudaGetSymbolAddress((void**)&h1, g_h1);
    cudaGetSymbolAddress((void**)&x2, g_x2);
    cudaGetSymbolAddress((void**)&h2, g_h2);
    cudaGetSymbolAddress(&cntp, g_cnt);

    // CSR build + dinv
    cudaMemsetAsync(cntp, 0, N_NODES * sizeof(int));
    k_count<<<(N_EDGES / 4 + 255) / 256, 256>>>(dstp);
    k_scan1<<<SCAN_BLK, 256>>>();
    k_scan2<<<1, 256>>>();
    k_scan3<<<SCAN_BLK, 256>>>();
    k_place<<<(N_EDGES / 4 + 255) / 256, 256>>>(srcp, dstp);

    const int gemm_blocks = (N_NODES + 63) / 64;

    // ---- layer 1 ----
    k_gemm<HID_C><<<gemm_blocks, 256>>>(x, W1, h1);
    k_agg1<<<(N_NODES * 32 + 255) / 256, 256>>>(b1);

    // ---- layer 2 ----
    k_gemm<OUT_C><<<gemm_blocks, 256>>>(x2, W2, h2);
    k_agg2<<<((N_NODES + 1) / 2 * 32 + 255) / 256, 256>>>(out, b2);
}

// round 5
// speedup vs baseline: 1.6406x; 1.4556x over previous
#include <cuda_runtime.h>
#include <stdint.h>

#define N_NODES 50000
#define N_EDGES 800000
#define IN_C    128
#define HID_C   128
#define OUT_C   64
#define SCAN_BLK 196   // ceil(50000/256)

typedef unsigned long long ull;
union F2U { ull u; float2 f; };

// ---------------- scratch (static device globals; no allocation) ------------
__device__ int   g_cnt   [N_NODES];
__device__ int   g_bsum  [SCAN_BLK];
__device__ int   g_boff  [SCAN_BLK];
__device__ int   g_rowptr[N_NODES + 1];
__device__ int   g_cursor[N_NODES];
__device__ int   g_csr   [N_EDGES];
__device__ float g_dinv  [N_NODES];
__device__ float g_h1    [N_NODES * HID_C];   // UNSCALED GEMM1 output
__device__ float g_x2    [N_NODES * HID_C];
__device__ float g_h2    [N_NODES * OUT_C];   // pre-scaled GEMM2 output

// ---------------- packed fp32x2 FMA ------------------------------------------
__device__ __forceinline__ ull fma2(ull a, ull b, ull c) {
    ull d;
    asm("fma.rn.f32x2 %0, %1, %2, %3;" : "=l"(d) : "l"(a), "l"(b), "l"(c));
    return d;
}

// ---------------- CSR build ---------------------------------------------------
__global__ void k_count(const int* __restrict__ dst) {
    int t = blockIdx.x * blockDim.x + threadIdx.x;
    if (t >= N_EDGES / 4) return;
    int4 d4 = reinterpret_cast<const int4*>(dst)[t];
    atomicAdd(&g_cnt[d4.x], 1);
    atomicAdd(&g_cnt[d4.y], 1);
    atomicAdd(&g_cnt[d4.z], 1);
    atomicAdd(&g_cnt[d4.w], 1);
}

__global__ void k_scan1() {
    __shared__ int s[256];
    int i = blockIdx.x * 256 + threadIdx.x;
    int c = (i < N_NODES) ? g_cnt[i] : 0;
    s[threadIdx.x] = c;
    __syncthreads();
#pragma unroll
    for (int o = 128; o > 0; o >>= 1) {
        if (threadIdx.x < o) s[threadIdx.x] += s[threadIdx.x + o];
        __syncthreads();
    }
    if (threadIdx.x == 0) g_bsum[blockIdx.x] = s[0];
}

__global__ void k_scan2() {
    __shared__ int s[256];
    int t = threadIdx.x;
    int own = (t < SCAN_BLK) ? g_bsum[t] : 0;
    s[t] = own;
    __syncthreads();
#pragma unroll
    for (int o = 1; o < 256; o <<= 1) {
        int v = (t >= o) ? s[t - o] : 0;
        __syncthreads();
        s[t] += v;
        __syncthreads();
    }
    if (t < SCAN_BLK) g_boff[t] = s[t] - own;      // exclusive block offsets
}

__global__ void k_scan3() {
    __shared__ int s[256];
    int t = threadIdx.x;
    int i = blockIdx.x * 256 + t;
    int c = (i < N_NODES) ? g_cnt[i] : 0;
    s[t] = c;
    __syncthreads();
#pragma unroll
    for (int o = 1; o < 256; o <<= 1) {
        int v = (t >= o) ? s[t - o] : 0;
        __syncthreads();
        s[t] += v;
        __syncthreads();
    }
    if (i < N_NODES) {
        int excl = g_boff[blockIdx.x] + s[t] - c;
        g_rowptr[i] = excl;
        g_cursor[i] = excl;
        g_dinv[i]   = rsqrtf(1.0f + (float)c);     // +1 self loop
        if (i == N_NODES - 1) g_rowptr[N_NODES] = excl + c;
    }
}

__global__ void k_place(const int* __restrict__ src, const int* __restrict__ dst) {
    int t = blockIdx.x * blockDim.x + threadIdx.x;
    if (t >= N_EDGES / 4) return;
    int4 d4 = reinterpret_cast<const int4*>(dst)[t];
    int4 s4 = reinterpret_cast<const int4*>(src)[t];
    int i0 = atomicAdd(&g_cursor[d4.x], 1);
    int i1 = atomicAdd(&g_cursor[d4.y], 1);
    int i2 = atomicAdd(&g_cursor[d4.z], 1);
    int i3 = atomicAdd(&g_cursor[d4.w], 1);
    g_csr[i0] = s4.x;
    g_csr[i1] = s4.y;
    g_csr[i2] = s4.z;
    g_csr[i3] = s4.w;
}

// ---------------- GEMM: H = (X @ W) [* dinv[row]] , packed fp32x2 along N ----
// BM=64 x COUT tile, 256 threads. Thread owns RPT rows x 4 cols (= 2 col pairs).
// w pairs come free from plain sW LDS.128 (conflict-free).
// a duplicated pairs (a,a) come from duplicated transposed X tile via broadcast
// LDS.128 (lane-invariant => conflict-free; dup cost paid on store side only).
template <int COUT, bool PRESCALE>
__global__ __launch_bounds__(256)
void k_gemm(const float* __restrict__ X, const float* __restrict__ W,
            float* __restrict__ H)
{
    constexpr int BM  = 64;
    constexpr int BK  = 32;
    constexpr int CQ  = COUT / 4;      // 32 / 16
    constexpr int RT  = 256 / CQ;      // 8 / 16
    constexpr int RPT = BM / RT;       // 8 / 4
    constexpr int XW  = 2 * BM + 4;    // 132 floats: 16B-aligned rows

    __shared__ float sXT2[BK][XW];     // duplicated transposed X tile
    __shared__ float sW  [BK][COUT];   // plain W tile

    const int tid  = threadIdx.x;
    const int colq = tid % CQ;
    const int rgrp = tid / CQ;
    const int row0 = blockIdx.x * BM;

    ull acc[RPT][2];
#pragma unroll
    for (int i = 0; i < RPT; i++) { acc[i][0] = 0ull; acc[i][1] = 0ull; }

    for (int k0 = 0; k0 < IN_C; k0 += BK) {
        // X tile: 64 rows x 32 cols, transposed + duplicated
#pragma unroll
        for (int i = tid; i < BM * BK / 4; i += 256) {
            int r = i >> 3, q = i & 7;
            int gr = row0 + r;
            float4 v = make_float4(0.f, 0.f, 0.f, 0.f);
            if (gr < N_NODES)
                v = *reinterpret_cast<const float4*>(X + (size_t)gr * IN_C + k0 + 4 * q);
            *reinterpret_cast<float2*>(&sXT2[4 * q + 0][2 * r]) = make_float2(v.x, v.x);
            *reinterpret_cast<float2*>(&sXT2[4 * q + 1][2 * r]) = make_float2(v.y, v.y);
            *reinterpret_cast<float2*>(&sXT2[4 * q + 2][2 * r]) = make_float2(v.z, v.z);
            *reinterpret_cast<float2*>(&sXT2[4 * q + 3][2 * r]) = make_float2(v.w, v.w);
        }
        // W tile: rows k0..k0+31 contiguous
        {
            const float4* wsrc = reinterpret_cast<const float4*>(W + (size_t)k0 * COUT);
            float4* wdst = reinterpret_cast<float4*>(&sW[0][0]);
#pragma unroll
            for (int i = tid; i < BK * COUT / 4; i += 256) wdst[i] = wsrc[i];
        }
        __syncthreads();

#pragma unroll
        for (int k = 0; k < BK; k++) {
            ulonglong2 w = *reinterpret_cast<const ulonglong2*>(&sW[k][4 * colq]);
            ull ad[RPT];
            const ulonglong2* aq =
                reinterpret_cast<const ulonglong2*>(&sXT2[k][2 * rgrp * RPT]);
#pragma unroll
            for (int p = 0; p < RPT / 2; p++) {
                ulonglong2 t = aq[p];
                ad[2 * p + 0] = t.x;
                ad[2 * p + 1] = t.y;
            }
#pragma unroll
            for (int i = 0; i < RPT; i++) {
                acc[i][0] = fma2(ad[i], w.x, acc[i][0]);
                acc[i][1] = fma2(ad[i], w.y, acc[i][1]);
            }
        }
        __syncthreads();
    }

#pragma unroll
    for (int i = 0; i < RPT; i++) {
        int gr = row0 + rgrp * RPT + i;
        if (gr < N_NODES) {
            F2U p0, p1;
            p0.u = acc[i][0]; p1.u = acc[i][1];
            float4 o = make_float4(p0.f.x, p0.f.y, p1.f.x, p1.f.y);
            if (PRESCALE) {
                float dv = g_dinv[gr];
                o.x *= dv; o.y *= dv; o.z *= dv; o.w *= dv;
            }
            *reinterpret_cast<float4*>(H + (size_t)gr * COUT + 4 * colq) = o;
        }
    }
}

// ---------------- layer-1 aggregation: warp per node, unroll 8 ----------------
// h1 is UNSCALED; apply dinv[s] per edge, dinv[n] for self + final scale.
__global__ __launch_bounds__(256)
void k_agg1(const float* __restrict__ b1) {
    int gw   = (blockIdx.x * 256 + threadIdx.x) >> 5;
    int lane = threadIdx.x & 31;
    if (gw >= N_NODES) return;

    const float4* Hq = reinterpret_cast<const float4*>(g_h1);
    float dvn = __ldg(&g_dinv[gw]);
    float4 sv = __ldcg(&Hq[(size_t)gw * 32 + lane]);
    float4 a0 = make_float4(sv.x * dvn, sv.y * dvn, sv.z * dvn, sv.w * dvn);
    float4 a1 = make_float4(0.f, 0.f, 0.f, 0.f);
    float4 a2 = make_float4(0.f, 0.f, 0.f, 0.f);
    float4 a3 = make_float4(0.f, 0.f, 0.f, 0.f);

    int e   = __ldg(&g_rowptr[gw]);
    int end = __ldg(&g_rowptr[gw + 1]);

    for (; e + 8 <= end; e += 8) {
        int s0 = __ldg(&g_csr[e + 0]), s1 = __ldg(&g_csr[e + 1]);
        int s2 = __ldg(&g_csr[e + 2]), s3 = __ldg(&g_csr[e + 3]);
        int s4 = __ldg(&g_csr[e + 4]), s5 = __ldg(&g_csr[e + 5]);
        int s6 = __ldg(&g_csr[e + 6]), s7 = __ldg(&g_csr[e + 7]);
        float d0 = __ldg(&g_dinv[s0]), d1 = __ldg(&g_dinv[s1]);
        float d2 = __ldg(&g_dinv[s2]), d3 = __ldg(&g_dinv[s3]);
        float d4 = __ldg(&g_dinv[s4]), d5 = __ldg(&g_dinv[s5]);
        float d6 = __ldg(&g_dinv[s6]), d7 = __ldg(&g_dinv[s7]);
        float4 v0 = __ldcg(&Hq[(size_t)s0 * 32 + lane]);
        float4 v1 = __ldcg(&Hq[(size_t)s1 * 32 + lane]);
        float4 v2 = __ldcg(&Hq[(size_t)s2 * 32 + lane]);
        float4 v3 = __ldcg(&Hq[(size_t)s3 * 32 + lane]);
        float4 v4 = __ldcg(&Hq[(size_t)s4 * 32 + lane]);
        float4 v5 = __ldcg(&Hq[(size_t)s5 * 32 + lane]);
        float4 v6 = __ldcg(&Hq[(size_t)s6 * 32 + lane]);
        float4 v7 = __ldcg(&Hq[(size_t)s7 * 32 + lane]);
        a0.x = fmaf(v0.x, d0, a0.x); a0.y = fmaf(v0.y, d0, a0.y);
        a0.z = fmaf(v0.z, d0, a0.z); a0.w = fmaf(v0.w, d0, a0.w);
        a1.x = fmaf(v1.x, d1, a1.x); a1.y = fmaf(v1.y, d1, a1.y);
        a1.z = fmaf(v1.z, d1, a1.z); a1.w = fmaf(v1.w, d1, a1.w);
        a2.x = fmaf(v2.x, d2, a2.x); a2.y = fmaf(v2.y, d2, a2.y);
        a2.z = fmaf(v2.z, d2, a2.z); a2.w = fmaf(v2.w, d2, a2.w);
        a3.x = fmaf(v3.x, d3, a3.x); a3.y = fmaf(v3.y, d3, a3.y);
        a3.z = fmaf(v3.z, d3, a3.z); a3.w = fmaf(v3.w, d3, a3.w);
        a0.x = fmaf(v4.x, d4, a0.x); a0.y = fmaf(v4.y, d4, a0.y);
        a0.z = fmaf(v4.z, d4, a0.z); a0.w = fmaf(v4.w, d4, a0.w);
        a1.x = fmaf(v5.x, d5, a1.x); a1.y = fmaf(v5.y, d5, a1.y);
        a1.z = fmaf(v5.z, d5, a1.z); a1.w = fmaf(v5.w, d5, a1.w);
        a2.x = fmaf(v6.x, d6, a2.x); a2.y = fmaf(v6.y, d6, a2.y);
        a2.z = fmaf(v6.z, d6, a2.z); a2.w = fmaf(v6.w, d6, a2.w);
        a3.x = fmaf(v7.x, d7, a3.x); a3.y = fmaf(v7.y, d7, a3.y);
        a3.z = fmaf(v7.z, d7, a3.z); a3.w = fmaf(v7.w, d7, a3.w);
    }
    for (; e < end; e++) {
        int s = __ldg(&g_csr[e]);
        float d = __ldg(&g_dinv[s]);
        float4 v = __ldcg(&Hq[(size_t)s * 32 + lane]);
        a0.x = fmaf(v.x, d, a0.x); a0.y = fmaf(v.y, d, a0.y);
        a0.z = fmaf(v.z, d, a0.z); a0.w = fmaf(v.w, d, a0.w);
    }
    a0.x += a1.x + a2.x + a3.x;
    a0.y += a1.y + a2.y + a3.y;
    a0.z += a1.z + a2.z + a3.z;
    a0.w += a1.w + a2.w + a3.w;

    float4 b = reinterpret_cast<const float4*>(b1)[lane];
    float4 o;
    o.x = fmaxf(fmaf(a0.x, dvn, b.x), 0.f);
    o.y = fmaxf(fmaf(a0.y, dvn, b.y), 0.f);
    o.z = fmaxf(fmaf(a0.z, dvn, b.z), 0.f);
    o.w = fmaxf(fmaf(a0.w, dvn, b.w), 0.f);
    reinterpret_cast<float4*>(g_x2)[(size_t)gw * 32 + lane] = o;
}

// ---------------- layer-2 aggregation: half-warp per node, unroll 8 -----------
// h2 IS pre-scaled by dinv[row].
__global__ __launch_bounds__(256)
void k_agg2(float* __restrict__ out, const float* __restrict__ b2) {
    int gw   = (blockIdx.x * 256 + threadIdx.x) >> 5;
    int lane = threadIdx.x & 31;
    int n    = gw * 2 + (lane >> 4);
    int hl   = lane & 15;
    if (n >= N_NODES) return;

    const float4* Hq = reinterpret_cast<const float4*>(g_h2);
    float4 a0 = __ldcg(&Hq[(size_t)n * 16 + hl]);      // self loop (pre-scaled)
    float4 a1 = make_float4(0.f, 0.f, 0.f, 0.f);
    float4 a2 = make_float4(0.f, 0.f, 0.f, 0.f);
    float4 a3 = make_float4(0.f, 0.f, 0.f, 0.f);

    int e   = __ldg(&g_rowptr[n]);
    int end = __ldg(&g_rowptr[n + 1]);

    for (; e + 8 <= end; e += 8) {
        int s0 = __ldg(&g_csr[e + 0]), s1 = __ldg(&g_csr[e + 1]);
        int s2 = __ldg(&g_csr[e + 2]), s3 = __ldg(&g_csr[e + 3]);
        int s4 = __ldg(&g_csr[e + 4]), s5 = __ldg(&g_csr[e + 5]);
        int s6 = __ldg(&g_csr[e + 6]), s7 = __ldg(&g_csr[e + 7]);
        float4 v0 = __ldcg(&Hq[(size_t)s0 * 16 + hl]);
        float4 v1 = __ldcg(&Hq[(size_t)s1 * 16 + hl]);
        float4 v2 = __ldcg(&Hq[(size_t)s2 * 16 + hl]);
        float4 v3 = __ldcg(&Hq[(size_t)s3 * 16 + hl]);
        float4 v4 = __ldcg(&Hq[(size_t)s4 * 16 + hl]);
        float4 v5 = __ldcg(&Hq[(size_t)s5 * 16 + hl]);
        float4 v6 = __ldcg(&Hq[(size_t)s6 * 16 + hl]);
        float4 v7 = __ldcg(&Hq[(size_t)s7 * 16 + hl]);
        a0.x += v0.x; a0.y += v0.y; a0.z += v0.z; a0.w += v0.w;
        a1.x += v1.x; a1.y += v1.y; a1.z += v1.z; a1.w += v1.w;
        a2.x += v2.x; a2.y += v2.y; a2.z += v2.z; a2.w += v2.w;
        a3.x += v3.x; a3.y += v3.y; a3.z += v3.z; a3.w += v3.w;
        a0.x += v4.x; a0.y += v4.y; a0.z += v4.z; a0.w += v4.w;
        a1.x += v5.x; a1.y += v5.y; a1.z += v5.z; a1.w += v5.w;
        a2.x += v6.x; a2.y += v6.y; a2.z += v6.z; a2.w += v6.w;
        a3.x += v7.x; a3.y += v7.y; a3.z += v7.z; a3.w += v7.w;
    }
    for (; e < end; e++) {
        int s = __ldg(&g_csr[e]);
        float4 v = __ldcg(&Hq[(size_t)s * 16 + hl]);
        a0.x += v.x; a0.y += v.y; a0.z += v.z; a0.w += v.w;
    }
    a0.x += a1.x + a2.x + a3.x;
    a0.y += a1.y + a2.y + a3.y;
    a0.z += a1.z + a2.z + a3.z;
    a0.w += a1.w + a2.w + a3.w;

    float dv = __ldg(&g_dinv[n]);
    float4 b = reinterpret_cast<const float4*>(b2)[hl];
    float4 o;
    o.x = fmaf(a0.x, dv, b.x);
    o.y = fmaf(a0.y, dv, b.y);
    o.z = fmaf(a0.z, dv, b.z);
    o.w = fmaf(a0.w, dv, b.w);
    reinterpret_cast<float4*>(out)[(size_t)n * 16 + hl] = o;
}

// ---------------- launch -------------------------------------------------------
extern "C" void kernel_launch(void* const* d_in, const int* in_sizes, int n_in,
                              void* d_out, int out_size)
{
    const float* x  = (const float*)d_in[0];
    const int*   ei = (const int*)  d_in[1];
    const float* W1 = (const float*)d_in[2];
    const float* b1 = (const float*)d_in[3];
    const float* W2 = (const float*)d_in[4];
    const float* b2 = (const float*)d_in[5];
    float* out = (float*)d_out;

    const int* srcp = ei;             // edge_index[0]
    const int* dstp = ei + N_EDGES;   // edge_index[1]

    float *h1, *x2, *h2;
    void* cntp;
    cudaGetSymbolAddress((void**)&h1, g_h1);
    cudaGetSymbolAddress((void**)&x2, g_x2);
    cudaGetSymbolAddress((void**)&h2, g_h2);
    cudaGetSymbolAddress(&cntp, g_cnt);

    // one-time side-stream + events (host resources only; reused across calls)
    static cudaStream_t s_aux = nullptr;
    static cudaEvent_t  e_fork = nullptr, e_join = nullptr;
    if (s_aux == nullptr) {
        cudaStreamCreateWithFlags(&s_aux, cudaStreamNonBlocking);
        cudaEventCreateWithFlags(&e_fork, cudaEventDisableTiming);
        cudaEventCreateWithFlags(&e_join, cudaEventDisableTiming);
    }

    const int gemm_blocks = (N_NODES + 63) / 64;

    // ---- fork: GEMM1 (no dinv dependency) runs parallel to CSR build ----
    cudaEventRecord(e_fork, 0);
    cudaStreamWaitEvent(s_aux, e_fork, 0);
    k_gemm<HID_C, false><<<gemm_blocks, 256, 0, s_aux>>>(x, W1, h1);
    cudaEventRecord(e_join, s_aux);

    // ---- CSR build + dinv on the main (legacy) stream ----
    cudaMemsetAsync(cntp, 0, N_NODES * sizeof(int));
    k_count<<<(N_EDGES / 4 + 255) / 256, 256>>>(dstp);
    k_scan1<<<SCAN_BLK, 256>>>();
    k_scan2<<<1, 256>>>();
    k_scan3<<<SCAN_BLK, 256>>>();
    k_place<<<(N_EDGES / 4 + 255) / 256, 256>>>(srcp, dstp);

    // ---- join, then layer 1 aggregation ----
    cudaStreamWaitEvent(0, e_join, 0);
    k_agg1<<<(N_NODES * 32 + 255) / 256, 256>>>(b1);

    // ---- layer 2 ----
    k_gemm<OUT_C, true><<<gemm_blocks, 256>>>(x2, W2, h2);
    k_agg2<<<((N_NODES + 1) / 2 * 32 + 255) / 256, 256>>>(out, b2);
}

// round 6
// speedup vs baseline: 1.7202x; 1.0485x over previous
#include <cuda_runtime.h>
#include <cuda_fp16.h>
#include <stdint.h>

#define N_NODES 50000
#define N_EDGES 800000
#define IN_C    128
#define HID_C   128
#define OUT_C   64
#define SCAN_BLK 196   // ceil(50000/256)

typedef unsigned long long ull;
union F2U { ull u; float2 f; };
union H4  { uint2 u; __half2 h[2]; };

// ---------------- scratch (static device globals; no allocation) ------------
__device__ int    g_cnt   [N_NODES];
__device__ int    g_bsum  [SCAN_BLK];
__device__ int    g_boff  [SCAN_BLK];
__device__ int    g_rowptr[N_NODES + 1];
__device__ int    g_cursor[N_NODES];
__device__ int    g_csr   [N_EDGES];
__device__ float  g_dinv  [N_NODES];
__device__ __half g_h1    [N_NODES * HID_C];   // UNSCALED GEMM1 output (fp16)
__device__ float  g_x2    [N_NODES * HID_C];
__device__ __half g_h2    [N_NODES * OUT_C];   // pre-scaled GEMM2 output (fp16)

// ---------------- packed fp32x2 FMA ------------------------------------------
__device__ __forceinline__ ull fma2(ull a, ull b, ull c) {
    ull d;
    asm("fma.rn.f32x2 %0, %1, %2, %3;" : "=l"(d) : "l"(a), "l"(b), "l"(c));
    return d;
}

// ---------------- CSR build ---------------------------------------------------
__global__ void k_count(const int* __restrict__ dst) {
    int t = blockIdx.x * blockDim.x + threadIdx.x;
    if (t >= N_EDGES / 4) return;
    int4 d4 = reinterpret_cast<const int4*>(dst)[t];
    atomicAdd(&g_cnt[d4.x], 1);
    atomicAdd(&g_cnt[d4.y], 1);
    atomicAdd(&g_cnt[d4.z], 1);
    atomicAdd(&g_cnt[d4.w], 1);
}

__global__ void k_scan1() {
    __shared__ int s[256];
    int i = blockIdx.x * 256 + threadIdx.x;
    int c = (i < N_NODES) ? g_cnt[i] : 0;
    s[threadIdx.x] = c;
    __syncthreads();
#pragma unroll
    for (int o = 128; o > 0; o >>= 1) {
        if (threadIdx.x < o) s[threadIdx.x] += s[threadIdx.x + o];
        __syncthreads();
    }
    if (threadIdx.x == 0) g_bsum[blockIdx.x] = s[0];
}

__global__ void k_scan2() {
    __shared__ int s[256];
    int t = threadIdx.x;
    int own = (t < SCAN_BLK) ? g_bsum[t] : 0;
    s[t] = own;
    __syncthreads();
#pragma unroll
    for (int o = 1; o < 256; o <<= 1) {
        int v = (t >= o) ? s[t - o] : 0;
        __syncthreads();
        s[t] += v;
        __syncthreads();
    }
    if (t < SCAN_BLK) g_boff[t] = s[t] - own;      // exclusive block offsets
}

__global__ void k_scan3() {
    __shared__ int s[256];
    int t = threadIdx.x;
    int i = blockIdx.x * 256 + t;
    int c = (i < N_NODES) ? g_cnt[i] : 0;
    s[t] = c;
    __syncthreads();
#pragma unroll
    for (int o = 1; o < 256; o <<= 1) {
        int v = (t >= o) ? s[t - o] : 0;
        __syncthreads();
        s[t] += v;
        __syncthreads();
    }
    if (i < N_NODES) {
        int excl = g_boff[blockIdx.x] + s[t] - c;
        g_rowptr[i] = excl;
        g_cursor[i] = excl;
        g_dinv[i]   = rsqrtf(1.0f + (float)c);     // +1 self loop
        if (i == N_NODES - 1) g_rowptr[N_NODES] = excl + c;
    }
}

__global__ void k_place(const int* __restrict__ src, const int* __restrict__ dst) {
    int t = blockIdx.x * blockDim.x + threadIdx.x;
    if (t >= N_EDGES / 4) return;
    int4 d4 = reinterpret_cast<const int4*>(dst)[t];
    int4 s4 = reinterpret_cast<const int4*>(src)[t];
    int i0 = atomicAdd(&g_cursor[d4.x], 1);
    int i1 = atomicAdd(&g_cursor[d4.y], 1);
    int i2 = atomicAdd(&g_cursor[d4.z], 1);
    int i3 = atomicAdd(&g_cursor[d4.w], 1);
    g_csr[i0] = s4.x;
    g_csr[i1] = s4.y;
    g_csr[i2] = s4.z;
    g_csr[i3] = s4.w;
}

// ---------------- GEMM: H = fp16( (X @ W) [* dinv[row]] ), packed fp32x2 -----
// BM=64 x COUT tile, 256 threads. Thread owns RPT rows x 4 cols (= 2 col pairs).
template <int COUT, bool PRESCALE>
__global__ __launch_bounds__(256)
void k_gemm(const float* __restrict__ X, const float* __restrict__ W,
            __half* __restrict__ H)
{
    constexpr int BM  = 64;
    constexpr int BK  = 32;
    constexpr int CQ  = COUT / 4;      // 32 / 16
    constexpr int RT  = 256 / CQ;      // 8 / 16
    constexpr int RPT = BM / RT;       // 8 / 4
    constexpr int XW  = 2 * BM + 4;    // 132 floats: 16B-aligned rows

    __shared__ float sXT2[BK][XW];     // duplicated transposed X tile
    __shared__ float sW  [BK][COUT];   // plain W tile

    const int tid  = threadIdx.x;
    const int colq = tid % CQ;
    const int rgrp = tid / CQ;
    const int row0 = blockIdx.x * BM;

    ull acc[RPT][2];
#pragma unroll
    for (int i = 0; i < RPT; i++) { acc[i][0] = 0ull; acc[i][1] = 0ull; }

    for (int k0 = 0; k0 < IN_C; k0 += BK) {
        // X tile: 64 rows x 32 cols, transposed + duplicated
#pragma unroll
        for (int i = tid; i < BM * BK / 4; i += 256) {
            int r = i >> 3, q = i & 7;
            int gr = row0 + r;
            float4 v = make_float4(0.f, 0.f, 0.f, 0.f);
            if (gr < N_NODES)
                v = *reinterpret_cast<const float4*>(X + (size_t)gr * IN_C + k0 + 4 * q);
            *reinterpret_cast<float2*>(&sXT2[4 * q + 0][2 * r]) = make_float2(v.x, v.x);
            *reinterpret_cast<float2*>(&sXT2[4 * q + 1][2 * r]) = make_float2(v.y, v.y);
            *reinterpret_cast<float2*>(&sXT2[4 * q + 2][2 * r]) = make_float2(v.z, v.z);
            *reinterpret_cast<float2*>(&sXT2[4 * q + 3][2 * r]) = make_float2(v.w, v.w);
        }
        // W tile: rows k0..k0+31 contiguous
        {
            const float4* wsrc = reinterpret_cast<const float4*>(W + (size_t)k0 * COUT);
            float4* wdst = reinterpret_cast<float4*>(&sW[0][0]);
#pragma unroll
            for (int i = tid; i < BK * COUT / 4; i += 256) wdst[i] = wsrc[i];
        }
        __syncthreads();

#pragma unroll
        for (int k = 0; k < BK; k++) {
            ulonglong2 w = *reinterpret_cast<const ulonglong2*>(&sW[k][4 * colq]);
            ull ad[RPT];
            const ulonglong2* aq =
                reinterpret_cast<const ulonglong2*>(&sXT2[k][2 * rgrp * RPT]);
#pragma unroll
            for (int p = 0; p < RPT / 2; p++) {
                ulonglong2 t = aq[p];
                ad[2 * p + 0] = t.x;
                ad[2 * p + 1] = t.y;
            }
#pragma unroll
            for (int i = 0; i < RPT; i++) {
                acc[i][0] = fma2(ad[i], w.x, acc[i][0]);
                acc[i][1] = fma2(ad[i], w.y, acc[i][1]);
            }
        }
        __syncthreads();
    }

#pragma unroll
    for (int i = 0; i < RPT; i++) {
        int gr = row0 + rgrp * RPT + i;
        if (gr < N_NODES) {
            F2U p0, p1;
            p0.u = acc[i][0]; p1.u = acc[i][1];
            float4 o = make_float4(p0.f.x, p0.f.y, p1.f.x, p1.f.y);
            if (PRESCALE) {
                float dv = g_dinv[gr];
                o.x *= dv; o.y *= dv; o.z *= dv; o.w *= dv;
            }
            H4 st;
            st.h[0] = __floats2half2_rn(o.x, o.y);
            st.h[1] = __floats2half2_rn(o.z, o.w);
            *reinterpret_cast<uint2*>(H + (size_t)gr * COUT + 4 * colq) = st.u;
        }
    }
}

// ---------------- layer-1 aggregation: warp per node, unroll 8 ----------------
// h1 fp16 UNSCALED; lane owns 4 channels (LDG.64 = 256B/row/warp).
__global__ __launch_bounds__(256)
void k_agg1(const float* __restrict__ b1) {
    int gw   = (blockIdx.x * 256 + threadIdx.x) >> 5;
    int lane = threadIdx.x & 31;
    if (gw >= N_NODES) return;

    const uint2* Hq = reinterpret_cast<const uint2*>(g_h1);

#define UNPACK4(r, f01, f23) { H4 _t; _t.u = (r); \
        f01 = __half22float2(_t.h[0]); f23 = __half22float2(_t.h[1]); }

    float dvn = __ldg(&g_dinv[gw]);
    float4 a0, a1, a2, a3;
    {
        uint2 r = __ldcg(&Hq[(size_t)gw * 32 + lane]);
        float2 f01, f23; UNPACK4(r, f01, f23);
        a0 = make_float4(f01.x * dvn, f01.y * dvn, f23.x * dvn, f23.y * dvn);
    }
    a1 = make_float4(0.f, 0.f, 0.f, 0.f);
    a2 = make_float4(0.f, 0.f, 0.f, 0.f);
    a3 = make_float4(0.f, 0.f, 0.f, 0.f);

    int e   = __ldg(&g_rowptr[gw]);
    int end = __ldg(&g_rowptr[gw + 1]);

    for (; e + 8 <= end; e += 8) {
        int s0 = __ldg(&g_csr[e + 0]), s1 = __ldg(&g_csr[e + 1]);
        int s2 = __ldg(&g_csr[e + 2]), s3 = __ldg(&g_csr[e + 3]);
        int s4 = __ldg(&g_csr[e + 4]), s5 = __ldg(&g_csr[e + 5]);
        int s6 = __ldg(&g_csr[e + 6]), s7 = __ldg(&g_csr[e + 7]);
        float d0 = __ldg(&g_dinv[s0]), d1 = __ldg(&g_dinv[s1]);
        float d2 = __ldg(&g_dinv[s2]), d3 = __ldg(&g_dinv[s3]);
        float d4 = __ldg(&g_dinv[s4]), d5 = __ldg(&g_dinv[s5]);
        float d6 = __ldg(&g_dinv[s6]), d7 = __ldg(&g_dinv[s7]);
        uint2 r0 = __ldcg(&Hq[(size_t)s0 * 32 + lane]);
        uint2 r1 = __ldcg(&Hq[(size_t)s1 * 32 + lane]);
        uint2 r2 = __ldcg(&Hq[(size_t)s2 * 32 + lane]);
        uint2 r3 = __ldcg(&Hq[(size_t)s3 * 32 + lane]);
        uint2 r4 = __ldcg(&Hq[(size_t)s4 * 32 + lane]);
        uint2 r5 = __ldcg(&Hq[(size_t)s5 * 32 + lane]);
        uint2 r6 = __ldcg(&Hq[(size_t)s6 * 32 + lane]);
        uint2 r7 = __ldcg(&Hq[(size_t)s7 * 32 + lane]);
        float2 f01, f23;
        UNPACK4(r0, f01, f23);
        a0.x = fmaf(f01.x, d0, a0.x); a0.y = fmaf(f01.y, d0, a0.y);
        a0.z = fmaf(f23.x, d0, a0.z); a0.w = fmaf(f23.y, d0, a0.w);
        UNPACK4(r1, f01, f23);
        a1.x = fmaf(f01.x, d1, a1.x); a1.y = fmaf(f01.y, d1, a1.y);
        a1.z = fmaf(f23.x, d1, a1.z); a1.w = fmaf(f23.y, d1, a1.w);
        UNPACK4(r2, f01, f23);
        a2.x = fmaf(f01.x, d2, a2.x); a2.y = fmaf(f01.y, d2, a2.y);
        a2.z = fmaf(f23.x, d2, a2.z); a2.w = fmaf(f23.y, d2, a2.w);
        UNPACK4(r3, f01, f23);
        a3.x = fmaf(f01.x, d3, a3.x); a3.y = fmaf(f01.y, d3, a3.y);
        a3.z = fmaf(f23.x, d3, a3.z); a3.w = fmaf(f23.y, d3, a3.w);
        UNPACK4(r4, f01, f23);
        a0.x = fmaf(f01.x, d4, a0.x); a0.y = fmaf(f01.y, d4, a0.y);
        a0.z = fmaf(f23.x, d4, a0.z); a0.w = fmaf(f23.y, d4, a0.w);
        UNPACK4(r5, f01, f23);
        a1.x = fmaf(f01.x, d5, a1.x); a1.y = fmaf(f01.y, d5, a1.y);
        a1.z = fmaf(f23.x, d5, a1.z); a1.w = fmaf(f23.y, d5, a1.w);
        UNPACK4(r6, f01, f23);
        a2.x = fmaf(f01.x, d6, a2.x); a2.y = fmaf(f01.y, d6, a2.y);
        a2.z = fmaf(f23.x, d6, a2.z); a2.w = fmaf(f23.y, d6, a2.w);
        UNPACK4(r7, f01, f23);
        a3.x = fmaf(f01.x, d7, a3.x); a3.y = fmaf(f01.y, d7, a3.y);
        a3.z = fmaf(f23.x, d7, a3.z); a3.w = fmaf(f23.y, d7, a3.w);
    }
    for (; e < end; e++) {
        int s = __ldg(&g_csr[e]);
        float d = __ldg(&g_dinv[s]);
        uint2 r = __ldcg(&Hq[(size_t)s * 32 + lane]);
        float2 f01, f23; UNPACK4(r, f01, f23);
        a0.x = fmaf(f01.x, d, a0.x); a0.y = fmaf(f01.y, d, a0.y);
        a0.z = fmaf(f23.x, d, a0.z); a0.w = fmaf(f23.y, d, a0.w);
    }
    a0.x += a1.x + a2.x + a3.x;
    a0.y += a1.y + a2.y + a3.y;
    a0.z += a1.z + a2.z + a3.z;
    a0.w += a1.w + a2.w + a3.w;

    float4 b = reinterpret_cast<const float4*>(b1)[lane];
    float4 o;
    o.x = fmaxf(fmaf(a0.x, dvn, b.x), 0.f);
    o.y = fmaxf(fmaf(a0.y, dvn, b.y), 0.f);
    o.z = fmaxf(fmaf(a0.z, dvn, b.z), 0.f);
    o.w = fmaxf(fmaf(a0.w, dvn, b.w), 0.f);
    reinterpret_cast<float4*>(g_x2)[(size_t)gw * 32 + lane] = o;
}

// ---------------- layer-2 aggregation: half-warp per node, unroll 8 -----------
// h2 fp16 pre-scaled; lane owns 4 channels (LDG.64 = 128B/row/half-warp).
__global__ __launch_bounds__(256)
void k_agg2(float* __restrict__ out, const float* __restrict__ b2) {
    int gw   = (blockIdx.x * 256 + threadIdx.x) >> 5;
    int lane = threadIdx.x & 31;
    int n    = gw * 2 + (lane >> 4);
    int hl   = lane & 15;
    if (n >= N_NODES) return;

    const uint2* Hq = reinterpret_cast<const uint2*>(g_h2);

    float4 a0, a1, a2, a3;
    {
        uint2 r = __ldcg(&Hq[(size_t)n * 16 + hl]);
        float2 f01, f23; UNPACK4(r, f01, f23);
        a0 = make_float4(f01.x, f01.y, f23.x, f23.y);   // self (pre-scaled)
    }
    a1 = make_float4(0.f, 0.f, 0.f, 0.f);
    a2 = make_float4(0.f, 0.f, 0.f, 0.f);
    a3 = make_float4(0.f, 0.f, 0.f, 0.f);

    int e   = __ldg(&g_rowptr[n]);
    int end = __ldg(&g_rowptr[n + 1]);

    for (; e + 8 <= end; e += 8) {
        int s0 = __ldg(&g_csr[e + 0]), s1 = __ldg(&g_csr[e + 1]);
        int s2 = __ldg(&g_csr[e + 2]), s3 = __ldg(&g_csr[e + 3]);
        int s4 = __ldg(&g_csr[e + 4]), s5 = __ldg(&g_csr[e + 5]);
        int s6 = __ldg(&g_csr[e + 6]), s7 = __ldg(&g_csr[e + 7]);
        uint2 r0 = __ldcg(&Hq[(size_t)s0 * 16 + hl]);
        uint2 r1 = __ldcg(&Hq[(size_t)s1 * 16 + hl]);
        uint2 r2 = __ldcg(&Hq[(size_t)s2 * 16 + hl]);
        uint2 r3 = __ldcg(&Hq[(size_t)s3 * 16 + hl]);
        uint2 r4 = __ldcg(&Hq[(size_t)s4 * 16 + hl]);
        uint2 r5 = __ldcg(&Hq[(size_t)s5 * 16 + hl]);
        uint2 r6 = __ldcg(&Hq[(size_t)s6 * 16 + hl]);
        uint2 r7 = __ldcg(&Hq[(size_t)s7 * 16 + hl]);
        float2 f01, f23;
        UNPACK4(r0, f01, f23);
        a0.x += f01.x; a0.y += f01.y; a0.z += f23.x; a0.w += f23.y;
        UNPACK4(r1, f01, f23);
        a1.x += f01.x; a1.y += f01.y; a1.z += f23.x; a1.w += f23.y;
        UNPACK4(r2, f01, f23);
        a2.x += f01.x; a2.y += f01.y; a2.z += f23.x; a2.w += f23.y;
        UNPACK4(r3, f01, f23);
        a3.x += f01.x; a3.y += f01.y; a3.z += f23.x; a3.w += f23.y;
        UNPACK4(r4, f01, f23);
        a0.x += f01.x; a0.y += f01.y; a0.z += f23.x; a0.w += f23.y;
        UNPACK4(r5, f01, f23);
        a1.x += f01.x; a1.y += f01.y; a1.z += f23.x; a1.w += f23.y;
        UNPACK4(r6, f01, f23);
        a2.x += f01.x; a2.y += f01.y; a2.z += f23.x; a2.w += f23.y;
        UNPACK4(r7, f01, f23);
        a3.x += f01.x; a3.y += f01.y; a3.z += f23.x; a3.w += f23.y;
    }
    for (; e < end; e++) {
        int s = __ldg(&g_csr[e]);
        uint2 r = __ldcg(&Hq[(size_t)s * 16 + hl]);
        float2 f01, f23; UNPACK4(r, f01, f23);
        a0.x += f01.x; a0.y += f01.y; a0.z += f23.x; a0.w += f23.y;
    }
    a0.x += a1.x + a2.x + a3.x;
    a0.y += a1.y + a2.y + a3.y;
    a0.z += a1.z + a2.z + a3.z;
    a0.w += a1.w + a2.w + a3.w;

    float dv = __ldg(&g_dinv[n]);
    float4 b = reinterpret_cast<const float4*>(b2)[hl];
    float4 o;
    o.x = fmaf(a0.x, dv, b.x);
    o.y = fmaf(a0.y, dv, b.y);
    o.z = fmaf(a0.z, dv, b.z);
    o.w = fmaf(a0.w, dv, b.w);
    reinterpret_cast<float4*>(out)[(size_t)n * 16 + hl] = o;
}

// ---------------- launch -------------------------------------------------------
extern "C" void kernel_launch(void* const* d_in, const int* in_sizes, int n_in,
                              void* d_out, int out_size)
{
    const float* x  = (const float*)d_in[0];
    const int*   ei = (const int*)  d_in[1];
    const float* W1 = (const float*)d_in[2];
    const float* b1 = (const float*)d_in[3];
    const float* W2 = (const float*)d_in[4];
    const float* b2 = (const float*)d_in[5];
    float* out = (float*)d_out;

    const int* srcp = ei;             // edge_index[0]
    const int* dstp = ei + N_EDGES;   // edge_index[1]

    __half *h1, *h2;
    float *x2;
    void* cntp;
    cudaGetSymbolAddress((void**)&h1, g_h1);
    cudaGetSymbolAddress((void**)&x2, g_x2);
    cudaGetSymbolAddress((void**)&h2, g_h2);
    cudaGetSymbolAddress(&cntp, g_cnt);

    // one-time side-stream + events (host resources only; reused across calls)
    static cudaStream_t s_aux = nullptr;
    static cudaEvent_t  e_fork = nullptr, e_join = nullptr;
    if (s_aux == nullptr) {
        cudaStreamCreateWithFlags(&s_aux, cudaStreamNonBlocking);
        cudaEventCreateWithFlags(&e_fork, cudaEventDisableTiming);
        cudaEventCreateWithFlags(&e_join, cudaEventDisableTiming);
    }

    const int gemm_blocks = (N_NODES + 63) / 64;

    // ---- fork: GEMM1 (no dinv dependency) runs parallel to CSR build ----
    cudaEventRecord(e_fork, 0);
    cudaStreamWaitEvent(s_aux, e_fork, 0);
    k_gemm<HID_C, false><<<gemm_blocks, 256, 0, s_aux>>>(x, W1, h1);
    cudaEventRecord(e_join, s_aux);

    // ---- CSR build + dinv on the main (legacy) stream ----
    cudaMemsetAsync(cntp, 0, N_NODES * sizeof(int));
    k_count<<<(N_EDGES / 4 + 255) / 256, 256>>>(dstp);
    k_scan1<<<SCAN_BLK, 256>>>();
    k_scan2<<<1, 256>>>();
    k_scan3<<<SCAN_BLK, 256>>>();
    k_place<<<(N_EDGES / 4 + 255) / 256, 256>>>(srcp, dstp);

    // ---- join, then layer 1 aggregation ----
    cudaStreamWaitEvent(0, e_join, 0);
    k_agg1<<<(N_NODES * 32 + 255) / 256, 256>>>(b1);

    // ---- layer 2 ----
    k_gemm<OUT_C, true><<<gemm_blocks, 256>>>(x2, W2, h2);
    k_agg2<<<((N_NODES + 1) / 2 * 32 + 255) / 256, 256>>>(out, b2);
}